// round 11
// baseline (speedup 1.0000x reference)
#include <cuda_runtime.h>
#include <cuda_fp16.h>
#include <math.h>
#include <stdint.h>

// Problem shape (fixed by the reference)
#define BQ 64
#define SQ 197
#define DQ 768
#define HQ 3072
#define MQ (BQ * SQ)  // 12608

// ---------------------------------------------------------------------------
// Device global scratch (no allocation allowed)
// ---------------------------------------------------------------------------
__device__ __half g_xh [(size_t)MQ * DQ];   // x in fp16
__device__ __half g_hh [(size_t)MQ * HQ];   // h (post-GELU) in fp16
__device__ __half g_q1 [(size_t)HQ * DQ];   // ternary w1 in fp16 (exact)
__device__ __half g_q2 [(size_t)DQ * HQ];   // ternary w2 in fp16 (exact)
__device__ float g_partial[1024];
__device__ float g_gamma[2];

__device__ __forceinline__ uint32_t smem_u32(const void* p) {
    uint32_t a;
    asm("{ .reg .u64 t; cvta.to.shared.u64 t, %1; cvt.u32.u64 %0, t; }"
        : "=r"(a) : "l"(p));
    return a;
}

// ---------------------------------------------------------------------------
// Fused pre-gamma prep: blocks 0-511 abs(w1), 512-1023 abs(w2), rest cvt x.
// ---------------------------------------------------------------------------
__global__ void prep1_kernel(const float* __restrict__ w1,
                             const float* __restrict__ w2, int nw,
                             const float* __restrict__ x,
                             __half* __restrict__ xh, int nx4) {
    int b = blockIdx.x;
    if (b < 1024) {
        const float* w = (b < 512) ? w1 : w2;
        int slot = (b < 512) ? 0 : 1;
        int rb = b & 511;
        __shared__ float sdata[256];
        float s = 0.0f;
        for (int i = rb * blockDim.x + threadIdx.x; i < nw;
             i += 512 * blockDim.x)
            s += fabsf(w[i]);
        sdata[threadIdx.x] = s;
        __syncthreads();
        #pragma unroll
        for (int off = 128; off > 0; off >>= 1) {
            if (threadIdx.x < off) sdata[threadIdx.x] += sdata[threadIdx.x + off];
            __syncthreads();
        }
        if (threadIdx.x == 0) g_partial[slot * 512 + rb] = sdata[0];
    } else {
        int i = (b - 1024) * blockDim.x + threadIdx.x;
        if (i >= nx4) return;
        float4 v = ((const float4*)x)[i];
        __half2 o0, o1;
        o0.x = __float2half_rn(v.x); o0.y = __float2half_rn(v.y);
        o1.x = __float2half_rn(v.z); o1.y = __float2half_rn(v.w);
        ((__half2*)xh)[2 * i + 0] = o0;
        ((__half2*)xh)[2 * i + 1] = o1;
    }
}

__global__ void finalize_gamma_kernel(int n1, int n2) {
    __shared__ float sdata[512];
    int t = threadIdx.x;
    sdata[t] = g_partial[t];
    __syncthreads();
    #pragma unroll
    for (int off = 256; off > 0; off >>= 1) {
        if (t < off) sdata[t] += sdata[t + off];
        __syncthreads();
    }
    if (t == 0) g_gamma[0] = sdata[0] / (float)n1 + 1e-5f;
    __syncthreads();
    sdata[t] = g_partial[512 + t];
    __syncthreads();
    #pragma unroll
    for (int off = 256; off > 0; off >>= 1) {
        if (t < off) sdata[t] += sdata[t + off];
        __syncthreads();
    }
    if (t == 0) g_gamma[1] = sdata[0] / (float)n2 + 1e-5f;
}

// ternarize BOTH weights to fp16 in one launch (4 elems per thread)
__global__ void quant_both_kernel(const float* __restrict__ w1,
                                  __half* __restrict__ q1,
                                  const float* __restrict__ w2,
                                  __half* __restrict__ q2, int n4) {
    int i = blockIdx.x * blockDim.x + threadIdx.x;
    if (i >= 2 * n4) return;
    const float* w;
    __half* q;
    int slot, j;
    if (i < n4) { w = w1; q = q1; slot = 0; j = i; }
    else        { w = w2; q = q2; slot = 1; j = i - n4; }
    float inv = 1.0f / g_gamma[slot];
    float4 v = ((const float4*)w)[j];
    __half2 o0, o1;
    o0.x = __float2half_rn(fminf(1.0f, fmaxf(-1.0f, rintf(v.x * inv))));
    o0.y = __float2half_rn(fminf(1.0f, fmaxf(-1.0f, rintf(v.y * inv))));
    o1.x = __float2half_rn(fminf(1.0f, fmaxf(-1.0f, rintf(v.z * inv))));
    o1.y = __float2half_rn(fminf(1.0f, fmaxf(-1.0f, rintf(v.w * inv))));
    ((__half2*)q)[2 * j + 0] = o0;
    ((__half2*)q)[2 * j + 1] = o1;
}

// ---------------------------------------------------------------------------
// HMMA GEMM: 128x128 CTA tile, 4 warps (128 threads), warp tile 64x64.
//   Cuts smem read traffic 33% vs 8x(64x32) (crossbar was the measured wall).
//   Analytic swizzle; double-buffered cp.async; 2 CTAs/SM.
// ---------------------------------------------------------------------------
template <int GELU_H>
__global__ __launch_bounds__(128, 2)
void hmma_gemm(const __half* __restrict__ A,
               const __half* __restrict__ B,
               const float* __restrict__ bias,
               void* __restrict__ Cout,
               int M, int N, int K, int gslot) {
    extern __shared__ char smem[];
    const uint32_t sb = smem_u32(smem);
    const int tid  = threadIdx.x;
    const int wid  = tid >> 5;
    const int lane = tid & 31;
    const int m0 = blockIdx.y * 128;
    const int n0 = blockIdx.x * 128;
    const int wm = wid & 1;    // 2 m-blocks of 64
    const int wn = wid >> 1;   // 2 n-blocks of 64

    const int nch = K >> 6;    // chunks of 64 fp16

    // per-thread constant swizzle pre-masks (bits 4..6)
    const uint32_t preA = (uint32_t)((((lane >> 4) << 4) ^ ((lane & 7) << 4)));
    const uint32_t preB = (uint32_t)((((lane & 8) << 1) ^ ((lane & 7) << 4)));
    const uint32_t rowA = (uint32_t)(wm * 64 + (lane & 15)) * 128u;
    const uint32_t rowB = (uint32_t)(wn * 64 + (lane & 7) + ((lane >> 4) << 3)) * 128u;

    float acc[4][8][4];
    #pragma unroll
    for (int i = 0; i < 4; i++)
        #pragma unroll
        for (int j = 0; j < 8; j++)
            #pragma unroll
            for (int k = 0; k < 4; k++) acc[i][j][k] = 0.0f;

    auto load_chunk = [&](int c) {
        const int buf = c & 1;
        const uint32_t offA = buf * 32768u;
        const uint32_t offB = offA + 16384u;
        const __half* Ag = A + (size_t)m0 * K + (size_t)c * 64;
        const __half* Bg = B + (size_t)n0 * K + (size_t)c * 64;
        #pragma unroll
        for (int t = 0; t < 8; t++) {
            int idx = tid + t * 128;            // 0..1023
            int row = idx >> 3;
            int c16 = idx & 7;
            uint32_t sw = (uint32_t)row * 128u
                        + (((uint32_t)c16 * 16u) ^ (((uint32_t)row & 7u) << 4));
            const void* ga = Ag + (size_t)row * K + c16 * 8;
            uint32_t na = (m0 + row < M) ? 16u : 0u;
            asm volatile("cp.async.cg.shared.global [%0], [%1], 16, %2;"
                         :: "r"(sb + offA + sw), "l"(ga), "r"(na));
            const void* gb = Bg + (size_t)row * K + c16 * 8;
            asm volatile("cp.async.cg.shared.global [%0], [%1], 16;"
                         :: "r"(sb + offB + sw), "l"(gb));
        }
        asm volatile("cp.async.commit_group;" ::: "memory");
    };

    auto compute_chunk = [&](int buf) {
        const uint32_t baseA = sb + buf * 32768u + rowA;
        const uint32_t baseB = sb + buf * 32768u + 16384u + rowB;
        #pragma unroll
        for (int kk = 0; kk < 64; kk += 16) {
            const uint32_t cA = ((uint32_t)(2 * kk)) ^ preA;
            const uint32_t cB = ((uint32_t)(2 * kk)) ^ preB;
            uint32_t a[4][4];
            #pragma unroll
            for (int mi = 0; mi < 4; mi++) {
                asm volatile(
                    "ldmatrix.sync.aligned.m8n8.x4.shared.b16 {%0,%1,%2,%3}, [%4];"
                    : "=r"(a[mi][0]), "=r"(a[mi][1]), "=r"(a[mi][2]), "=r"(a[mi][3])
                    : "r"(baseA + (uint32_t)(mi * 2048) + cA));
            }
            uint32_t b[8][2];
            #pragma unroll
            for (int nj = 0; nj < 4; nj++) {
                uint32_t b0, b1, b2, b3;
                asm volatile(
                    "ldmatrix.sync.aligned.m8n8.x4.shared.b16 {%0,%1,%2,%3}, [%4];"
                    : "=r"(b0), "=r"(b1), "=r"(b2), "=r"(b3)
                    : "r"(baseB + (uint32_t)(nj * 2048) + cB));
                b[nj * 2 + 0][0] = b0; b[nj * 2 + 0][1] = b1;
                b[nj * 2 + 1][0] = b2; b[nj * 2 + 1][1] = b3;
            }
            #pragma unroll
            for (int mi = 0; mi < 4; mi++)
                #pragma unroll
                for (int ni = 0; ni < 8; ni++)
                    asm volatile(
                        "mma.sync.aligned.m16n8k16.row.col.f32.f16.f16.f32 "
                        "{%0,%1,%2,%3}, {%4,%5,%6,%7}, {%8,%9}, {%0,%1,%2,%3};"
                        : "+f"(acc[mi][ni][0]), "+f"(acc[mi][ni][1]),
                          "+f"(acc[mi][ni][2]), "+f"(acc[mi][ni][3])
                        : "r"(a[mi][0]), "r"(a[mi][1]), "r"(a[mi][2]), "r"(a[mi][3]),
                          "r"(b[ni][0]), "r"(b[ni][1]));
        }
    };

    load_chunk(0);
    for (int c = 0; c < nch; c++) {
        if (c + 1 < nch) {
            load_chunk(c + 1);
            asm volatile("cp.async.wait_group 1;" ::: "memory");
        } else {
            asm volatile("cp.async.wait_group 0;" ::: "memory");
        }
        __syncthreads();
        compute_chunk(c & 1);
        __syncthreads();
    }

    // ---- epilogue: gamma * acc + bias (+ exact GELU -> fp16) ----
    const float gamma = g_gamma[gslot];
    #pragma unroll
    for (int mi = 0; mi < 4; mi++) {
        #pragma unroll
        for (int half = 0; half < 2; half++) {
            int gr = m0 + wm * 64 + mi * 16 + (lane >> 2) + half * 8;
            if (gr >= M) continue;
            #pragma unroll
            for (int ni = 0; ni < 8; ni++) {
                int gc = n0 + wn * 64 + ni * 8 + 2 * (lane & 3);
                float v0 = acc[mi][ni][half * 2 + 0] * gamma + bias[gc];
                float v1 = acc[mi][ni][half * 2 + 1] * gamma + bias[gc + 1];
                if (GELU_H) {
                    v0 = 0.5f * v0 * (1.0f + erff(v0 * 0.70710678118654752f));
                    v1 = 0.5f * v1 * (1.0f + erff(v1 * 0.70710678118654752f));
                    __half2 p;
                    p.x = __float2half_rn(v0);
                    p.y = __float2half_rn(v1);
                    *(__half2*)((__half*)Cout + (size_t)gr * N + gc) = p;
                } else {
                    *(float2*)((float*)Cout + (size_t)gr * N + gc) =
                        make_float2(v0, v1);
                }
            }
        }
    }
}

// ---------------------------------------------------------------------------
// Launch
// ---------------------------------------------------------------------------
extern "C" void kernel_launch(void* const* d_in, const int* in_sizes, int n_in,
                              void* d_out, int out_size) {
    const float* x  = (const float*)d_in[0];
    const float* w1 = (const float*)d_in[1];
    const float* b1 = (const float*)d_in[2];
    const float* w2 = (const float*)d_in[3];
    const float* b2 = (const float*)d_in[4];
    float* out = (float*)d_out;

    __half *p_xh, *p_hh, *p_q1, *p_q2;
    cudaGetSymbolAddress((void**)&p_xh, g_xh);
    cudaGetSymbolAddress((void**)&p_hh, g_hh);
    cudaGetSymbolAddress((void**)&p_q1, g_q1);
    cudaGetSymbolAddress((void**)&p_q2, g_q2);

    const int NW = HQ * DQ;          // 2359296
    const int NX4 = MQ * DQ / 4;     // 2420736
    const int SMEM_DYN = 2 * 32768;  // 64KB

    static bool attr_done = false;
    if (!attr_done) {
        cudaFuncSetAttribute(hmma_gemm<1>,
            cudaFuncAttributeMaxDynamicSharedMemorySize, SMEM_DYN);
        cudaFuncSetAttribute(hmma_gemm<0>,
            cudaFuncAttributeMaxDynamicSharedMemorySize, SMEM_DYN);
        attr_done = true;
    }

    prep1_kernel<<<1024 + (NX4 + 255) / 256, 256>>>(w1, w2, NW, x, p_xh, NX4);
    finalize_gamma_kernel<<<1, 512>>>(NW, NW);
    quant_both_kernel<<<(2 * (NW / 4) + 255) / 256, 256>>>(w1, p_q1, w2, p_q2,
                                                           NW / 4);

    // GEMM1: [M, 768] x [H, 768]^T -> gelu -> fp16 h
    {
        dim3 grid(HQ / 128, (MQ + 127) / 128);
        hmma_gemm<1><<<grid, 128, SMEM_DYN>>>(
            p_xh, p_q1, b1, (void*)p_hh, MQ, HQ, DQ, 0);
    }
    // GEMM2: [M, 3072] x [D, 3072]^T -> + b2 -> out fp32
    {
        dim3 grid(DQ / 128, (MQ + 127) / 128);
        hmma_gemm<0><<<grid, 128, SMEM_DYN>>>(
            p_hh, p_q2, b2, (void*)out, MQ, DQ, HQ, 1);
    }
}

// round 12
// speedup vs baseline: 1.0427x; 1.0427x over previous
#include <cuda_runtime.h>
#include <cuda_fp16.h>
#include <math.h>
#include <stdint.h>

// Problem shape (fixed by the reference)
#define BQ 64
#define SQ 197
#define DQ 768
#define HQ 3072
#define MQ (BQ * SQ)  // 12608

// ---------------------------------------------------------------------------
// Device global scratch (no allocation allowed)
// ---------------------------------------------------------------------------
__device__ __half g_xh [(size_t)MQ * DQ];   // x in fp16
__device__ __half g_hh [(size_t)MQ * HQ];   // h (post-GELU) in fp16
__device__ __half g_q1 [(size_t)HQ * DQ];   // ternary w1 in fp16 (exact)
__device__ __half g_q2 [(size_t)DQ * HQ];   // ternary w2 in fp16 (exact)
__device__ float g_partial[1024];
__device__ float g_gamma[2];

__device__ __forceinline__ uint32_t smem_u32(const void* p) {
    uint32_t a;
    asm("{ .reg .u64 t; cvta.to.shared.u64 t, %1; cvt.u32.u64 %0, t; }"
        : "=r"(a) : "l"(p));
    return a;
}

__device__ __forceinline__ uint32_t pack_h2(float a, float b) {
    __half2 p;
    p.x = __float2half_rn(a);
    p.y = __float2half_rn(b);
    return *(uint32_t*)&p;
}

// ---------------------------------------------------------------------------
// Fused pre-gamma prep: blocks 0-511 abs(w1), 512-1023 abs(w2), rest cvt x.
// cvt path: one 8B store per 4 elements (was 2x4B).
// ---------------------------------------------------------------------------
__global__ void prep1_kernel(const float* __restrict__ w1,
                             const float* __restrict__ w2, int nw,
                             const float* __restrict__ x,
                             __half* __restrict__ xh, int nx4) {
    int b = blockIdx.x;
    if (b < 1024) {
        const float* w = (b < 512) ? w1 : w2;
        int slot = (b < 512) ? 0 : 1;
        int rb = b & 511;
        __shared__ float sdata[256];
        float s = 0.0f;
        for (int i = rb * blockDim.x + threadIdx.x; i < nw;
             i += 512 * blockDim.x)
            s += fabsf(w[i]);
        sdata[threadIdx.x] = s;
        __syncthreads();
        #pragma unroll
        for (int off = 128; off > 0; off >>= 1) {
            if (threadIdx.x < off) sdata[threadIdx.x] += sdata[threadIdx.x + off];
            __syncthreads();
        }
        if (threadIdx.x == 0) g_partial[slot * 512 + rb] = sdata[0];
    } else {
        int i = (b - 1024) * blockDim.x + threadIdx.x;
        if (i >= nx4) return;
        float4 v = ((const float4*)x)[i];
        uint2 st = make_uint2(pack_h2(v.x, v.y), pack_h2(v.z, v.w));
        ((uint2*)xh)[i] = st;
    }
}

__global__ void finalize_gamma_kernel(int n1, int n2) {
    __shared__ float sdata[512];
    int t = threadIdx.x;
    sdata[t] = g_partial[t];
    __syncthreads();
    #pragma unroll
    for (int off = 256; off > 0; off >>= 1) {
        if (t < off) sdata[t] += sdata[t + off];
        __syncthreads();
    }
    if (t == 0) g_gamma[0] = sdata[0] / (float)n1 + 1e-5f;
    __syncthreads();
    sdata[t] = g_partial[512 + t];
    __syncthreads();
    #pragma unroll
    for (int off = 256; off > 0; off >>= 1) {
        if (t < off) sdata[t] += sdata[t + off];
        __syncthreads();
    }
    if (t == 0) g_gamma[1] = sdata[0] / (float)n2 + 1e-5f;
}

// ternarize BOTH weights to fp16 in one launch; one 8B store per 4 elems
__global__ void quant_both_kernel(const float* __restrict__ w1,
                                  __half* __restrict__ q1,
                                  const float* __restrict__ w2,
                                  __half* __restrict__ q2, int n4) {
    int i = blockIdx.x * blockDim.x + threadIdx.x;
    if (i >= 2 * n4) return;
    const float* w;
    __half* q;
    int slot, j;
    if (i < n4) { w = w1; q = q1; slot = 0; j = i; }
    else        { w = w2; q = q2; slot = 1; j = i - n4; }
    float inv = 1.0f / g_gamma[slot];
    float4 v = ((const float4*)w)[j];
    float t0 = fminf(1.0f, fmaxf(-1.0f, rintf(v.x * inv)));
    float t1 = fminf(1.0f, fmaxf(-1.0f, rintf(v.y * inv)));
    float t2 = fminf(1.0f, fmaxf(-1.0f, rintf(v.z * inv)));
    float t3 = fminf(1.0f, fmaxf(-1.0f, rintf(v.w * inv)));
    uint2 st = make_uint2(pack_h2(t0, t1), pack_h2(t2, t3));
    ((uint2*)q)[j] = st;
}

// ---------------------------------------------------------------------------
// HMMA GEMM (R10 engine, byte-identical): 128x128 CTA tile, 8 warps x (64x32),
// analytic swizzle, double-buffered cp.async, 2 CTAs/SM.
// ---------------------------------------------------------------------------
template <int GELU_H>
__global__ __launch_bounds__(256, 2)
void hmma_gemm(const __half* __restrict__ A,
               const __half* __restrict__ B,
               const float* __restrict__ bias,
               void* __restrict__ Cout,
               int M, int N, int K, int gslot) {
    extern __shared__ char smem[];
    const uint32_t sb = smem_u32(smem);
    const int tid  = threadIdx.x;
    const int wid  = tid >> 5;
    const int lane = tid & 31;
    const int m0 = blockIdx.y * 128;
    const int n0 = blockIdx.x * 128;
    const int wm = wid & 1;    // 2 m-blocks of 64
    const int wn = wid >> 1;   // 4 n-blocks of 32

    const int nch = K >> 6;    // chunks of 64 fp16

    // per-thread constant swizzle pre-masks (bits 4..6)
    const uint32_t preA = (uint32_t)((((lane >> 4) << 4) ^ ((lane & 7) << 4)));
    const uint32_t preB = (uint32_t)((((lane & 8) << 1) ^ ((lane & 7) << 4)));
    const uint32_t rowA = (uint32_t)(wm * 64 + (lane & 15)) * 128u;
    const uint32_t rowB = (uint32_t)(wn * 32 + (lane & 7) + ((lane >> 4) << 3)) * 128u;

    float acc[4][4][4];
    #pragma unroll
    for (int i = 0; i < 4; i++)
        #pragma unroll
        for (int j = 0; j < 4; j++)
            #pragma unroll
            for (int k = 0; k < 4; k++) acc[i][j][k] = 0.0f;

    auto load_chunk = [&](int c) {
        const int buf = c & 1;
        const uint32_t offA = buf * 32768u;
        const uint32_t offB = offA + 16384u;
        const __half* Ag = A + (size_t)m0 * K + (size_t)c * 64;
        const __half* Bg = B + (size_t)n0 * K + (size_t)c * 64;
        #pragma unroll
        for (int t = 0; t < 4; t++) {
            int idx = tid + t * 256;            // 0..1023
            int row = idx >> 3;
            int c16 = idx & 7;
            uint32_t sw = (uint32_t)row * 128u
                        + (((uint32_t)c16 * 16u) ^ (((uint32_t)row & 7u) << 4));
            const void* ga = Ag + (size_t)row * K + c16 * 8;
            uint32_t na = (m0 + row < M) ? 16u : 0u;
            asm volatile("cp.async.cg.shared.global [%0], [%1], 16, %2;"
                         :: "r"(sb + offA + sw), "l"(ga), "r"(na));
            const void* gb = Bg + (size_t)row * K + c16 * 8;
            asm volatile("cp.async.cg.shared.global [%0], [%1], 16;"
                         :: "r"(sb + offB + sw), "l"(gb));
        }
        asm volatile("cp.async.commit_group;" ::: "memory");
    };

    auto compute_chunk = [&](int buf) {
        const uint32_t baseA = sb + buf * 32768u + rowA;
        const uint32_t baseB = sb + buf * 32768u + 16384u + rowB;
        #pragma unroll
        for (int kk = 0; kk < 64; kk += 16) {
            const uint32_t cA = ((uint32_t)(2 * kk)) ^ preA;
            const uint32_t cB = ((uint32_t)(2 * kk)) ^ preB;
            uint32_t a[4][4];
            #pragma unroll
            for (int mi = 0; mi < 4; mi++) {
                asm volatile(
                    "ldmatrix.sync.aligned.m8n8.x4.shared.b16 {%0,%1,%2,%3}, [%4];"
                    : "=r"(a[mi][0]), "=r"(a[mi][1]), "=r"(a[mi][2]), "=r"(a[mi][3])
                    : "r"(baseA + (uint32_t)(mi * 2048) + cA));
            }
            uint32_t b[4][2];
            #pragma unroll
            for (int nj = 0; nj < 2; nj++) {
                uint32_t b0, b1, b2, b3;
                asm volatile(
                    "ldmatrix.sync.aligned.m8n8.x4.shared.b16 {%0,%1,%2,%3}, [%4];"
                    : "=r"(b0), "=r"(b1), "=r"(b2), "=r"(b3)
                    : "r"(baseB + (uint32_t)(nj * 2048) + cB));
                b[nj * 2 + 0][0] = b0; b[nj * 2 + 0][1] = b1;
                b[nj * 2 + 1][0] = b2; b[nj * 2 + 1][1] = b3;
            }
            #pragma unroll
            for (int mi = 0; mi < 4; mi++)
                #pragma unroll
                for (int ni = 0; ni < 4; ni++)
                    asm volatile(
                        "mma.sync.aligned.m16n8k16.row.col.f32.f16.f16.f32 "
                        "{%0,%1,%2,%3}, {%4,%5,%6,%7}, {%8,%9}, {%0,%1,%2,%3};"
                        : "+f"(acc[mi][ni][0]), "+f"(acc[mi][ni][1]),
                          "+f"(acc[mi][ni][2]), "+f"(acc[mi][ni][3])
                        : "r"(a[mi][0]), "r"(a[mi][1]), "r"(a[mi][2]), "r"(a[mi][3]),
                          "r"(b[ni][0]), "r"(b[ni][1]));
        }
    };

    load_chunk(0);
    for (int c = 0; c < nch; c++) {
        if (c + 1 < nch) {
            load_chunk(c + 1);
            asm volatile("cp.async.wait_group 1;" ::: "memory");
        } else {
            asm volatile("cp.async.wait_group 0;" ::: "memory");
        }
        __syncthreads();
        compute_chunk(c & 1);
        __syncthreads();
    }

    // ---- epilogue: gamma * acc + bias (+ exact GELU -> fp16) ----
    const float gamma = g_gamma[gslot];
    #pragma unroll
    for (int mi = 0; mi < 4; mi++) {
        #pragma unroll
        for (int half = 0; half < 2; half++) {
            int gr = m0 + wm * 64 + mi * 16 + (lane >> 2) + half * 8;
            if (gr >= M) continue;
            #pragma unroll
            for (int ni = 0; ni < 4; ni++) {
                int gc = n0 + wn * 32 + ni * 8 + 2 * (lane & 3);
                float v0 = acc[mi][ni][half * 2 + 0] * gamma + bias[gc];
                float v1 = acc[mi][ni][half * 2 + 1] * gamma + bias[gc + 1];
                if (GELU_H) {
                    v0 = 0.5f * v0 * (1.0f + erff(v0 * 0.70710678118654752f));
                    v1 = 0.5f * v1 * (1.0f + erff(v1 * 0.70710678118654752f));
                    __half2 p;
                    p.x = __float2half_rn(v0);
                    p.y = __float2half_rn(v1);
                    *(__half2*)((__half*)Cout + (size_t)gr * N + gc) = p;
                } else {
                    *(float2*)((float*)Cout + (size_t)gr * N + gc) =
                        make_float2(v0, v1);
                }
            }
        }
    }
}

// ---------------------------------------------------------------------------
// Launch (5-launch structure kept so ncu lands on gemm1)
// ---------------------------------------------------------------------------
extern "C" void kernel_launch(void* const* d_in, const int* in_sizes, int n_in,
                              void* d_out, int out_size) {
    const float* x  = (const float*)d_in[0];
    const float* w1 = (const float*)d_in[1];
    const float* b1 = (const float*)d_in[2];
    const float* w2 = (const float*)d_in[3];
    const float* b2 = (const float*)d_in[4];
    float* out = (float*)d_out;

    __half *p_xh, *p_hh, *p_q1, *p_q2;
    cudaGetSymbolAddress((void**)&p_xh, g_xh);
    cudaGetSymbolAddress((void**)&p_hh, g_hh);
    cudaGetSymbolAddress((void**)&p_q1, g_q1);
    cudaGetSymbolAddress((void**)&p_q2, g_q2);

    const int NW = HQ * DQ;          // 2359296
    const int NX4 = MQ * DQ / 4;     // 2420736
    const int SMEM_DYN = 2 * 32768;  // 64KB

    static bool attr_done = false;
    if (!attr_done) {
        cudaFuncSetAttribute(hmma_gemm<1>,
            cudaFuncAttributeMaxDynamicSharedMemorySize, SMEM_DYN);
        cudaFuncSetAttribute(hmma_gemm<0>,
            cudaFuncAttributeMaxDynamicSharedMemorySize, SMEM_DYN);
        attr_done = true;
    }

    prep1_kernel<<<1024 + (NX4 + 255) / 256, 256>>>(w1, w2, NW, x, p_xh, NX4);
    finalize_gamma_kernel<<<1, 512>>>(NW, NW);
    quant_both_kernel<<<(2 * (NW / 4) + 255) / 256, 256>>>(w1, p_q1, w2, p_q2,
                                                           NW / 4);

    // GEMM1: [M, 768] x [H, 768]^T -> gelu -> fp16 h
    {
        dim3 grid(HQ / 128, (MQ + 127) / 128);
        hmma_gemm<1><<<grid, 256, SMEM_DYN>>>(
            p_xh, p_q1, b1, (void*)p_hh, MQ, HQ, DQ, 0);
    }
    // GEMM2: [M, 3072] x [D, 3072]^T -> + b2 -> out fp32
    {
        dim3 grid(DQ / 128, (MQ + 127) / 128);
        hmma_gemm<0><<<grid, 256, SMEM_DYN>>>(
            p_hh, p_q2, b2, (void*)out, MQ, DQ, HQ, 1);
    }
}

// round 13
// speedup vs baseline: 1.0687x; 1.0249x over previous
#include <cuda_runtime.h>
#include <cuda_fp16.h>
#include <math.h>
#include <stdint.h>

// Problem shape (fixed by the reference)
#define BQ 64
#define SQ 197
#define DQ 768
#define HQ 3072
#define MQ (BQ * SQ)  // 12608 = 197 * 64 (M-tiles of 64 are exact)

// ---------------------------------------------------------------------------
// Device global scratch (no allocation allowed)
// ---------------------------------------------------------------------------
__device__ __half g_xh [(size_t)MQ * DQ];   // x in fp16
__device__ __half g_hh [(size_t)MQ * HQ];   // h (post-GELU) in fp16
__device__ __half g_q1 [(size_t)HQ * DQ];   // ternary w1 in fp16 (exact)
__device__ __half g_q2 [(size_t)DQ * HQ];   // ternary w2 in fp16 (exact)
__device__ float g_partial[1024];
__device__ float g_gamma[2];

__device__ __forceinline__ uint32_t smem_u32(const void* p) {
    uint32_t a;
    asm("{ .reg .u64 t; cvta.to.shared.u64 t, %1; cvt.u32.u64 %0, t; }"
        : "=r"(a) : "l"(p));
    return a;
}

__device__ __forceinline__ uint32_t pack_h2(float a, float b) {
    __half2 p;
    p.x = __float2half_rn(a);
    p.y = __float2half_rn(b);
    return *(uint32_t*)&p;
}

// ---------------------------------------------------------------------------
// Fused pre-gamma prep: blocks 0-511 abs(w1), 512-1023 abs(w2), rest cvt x.
// ---------------------------------------------------------------------------
__global__ void prep1_kernel(const float* __restrict__ w1,
                             const float* __restrict__ w2, int nw,
                             const float* __restrict__ x,
                             __half* __restrict__ xh, int nx4) {
    int b = blockIdx.x;
    if (b < 1024) {
        const float* w = (b < 512) ? w1 : w2;
        int slot = (b < 512) ? 0 : 1;
        int rb = b & 511;
        __shared__ float sdata[256];
        float s = 0.0f;
        for (int i = rb * blockDim.x + threadIdx.x; i < nw;
             i += 512 * blockDim.x)
            s += fabsf(w[i]);
        sdata[threadIdx.x] = s;
        __syncthreads();
        #pragma unroll
        for (int off = 128; off > 0; off >>= 1) {
            if (threadIdx.x < off) sdata[threadIdx.x] += sdata[threadIdx.x + off];
            __syncthreads();
        }
        if (threadIdx.x == 0) g_partial[slot * 512 + rb] = sdata[0];
    } else {
        int i = (b - 1024) * blockDim.x + threadIdx.x;
        if (i >= nx4) return;
        float4 v = ((const float4*)x)[i];
        uint2 st = make_uint2(pack_h2(v.x, v.y), pack_h2(v.z, v.w));
        ((uint2*)xh)[i] = st;
    }
}

__global__ void finalize_gamma_kernel(int n1, int n2) {
    __shared__ float sdata[512];
    int t = threadIdx.x;
    sdata[t] = g_partial[t];
    __syncthreads();
    #pragma unroll
    for (int off = 256; off > 0; off >>= 1) {
        if (t < off) sdata[t] += sdata[t + off];
        __syncthreads();
    }
    if (t == 0) g_gamma[0] = sdata[0] / (float)n1 + 1e-5f;
    __syncthreads();
    sdata[t] = g_partial[512 + t];
    __syncthreads();
    #pragma unroll
    for (int off = 256; off > 0; off >>= 1) {
        if (t < off) sdata[t] += sdata[t + off];
        __syncthreads();
    }
    if (t == 0) g_gamma[1] = sdata[0] / (float)n2 + 1e-5f;
}

// ternarize BOTH weights to fp16 in one launch; one 8B store per 4 elems
__global__ void quant_both_kernel(const float* __restrict__ w1,
                                  __half* __restrict__ q1,
                                  const float* __restrict__ w2,
                                  __half* __restrict__ q2, int n4) {
    int i = blockIdx.x * blockDim.x + threadIdx.x;
    if (i >= 2 * n4) return;
    const float* w;
    __half* q;
    int slot, j;
    if (i < n4) { w = w1; q = q1; slot = 0; j = i; }
    else        { w = w2; q = q2; slot = 1; j = i - n4; }
    float inv = 1.0f / g_gamma[slot];
    float4 v = ((const float4*)w)[j];
    float t0 = fminf(1.0f, fmaxf(-1.0f, rintf(v.x * inv)));
    float t1 = fminf(1.0f, fmaxf(-1.0f, rintf(v.y * inv)));
    float t2 = fminf(1.0f, fmaxf(-1.0f, rintf(v.z * inv)));
    float t3 = fminf(1.0f, fmaxf(-1.0f, rintf(v.w * inv)));
    uint2 st = make_uint2(pack_h2(t0, t1), pack_h2(t2, t3));
    ((uint2*)q)[j] = st;
}

// ---------------------------------------------------------------------------
// HMMA GEMM: 64x128 CTA tile, 128 threads (4 warps x 64x32), 4 CTAs/SM.
//   Per-warp workload identical to the proven R10 engine; CTA-level
//   parallelism x2 to hide barrier/epilogue latency.
//   Stage = A(64x64, 8KB) + B(128x64, 16KB) = 24KB; double-buffered.
// ---------------------------------------------------------------------------
template <int GELU_H>
__global__ __launch_bounds__(128, 4)
void hmma_gemm(const __half* __restrict__ A,
               const __half* __restrict__ B,
               const float* __restrict__ bias,
               void* __restrict__ Cout,
               int M, int N, int K, int gslot) {
    extern __shared__ char smem[];
    const uint32_t sb = smem_u32(smem);
    const int tid  = threadIdx.x;
    const int wid  = tid >> 5;      // 0..3 -> n-block of 32
    const int lane = tid & 31;
    const int m0 = blockIdx.y * 64;
    const int n0 = blockIdx.x * 128;
    const int wn = wid;

    const int nch = K >> 6;    // chunks of 64 fp16

    // per-thread constant swizzle pre-masks (bits 4..6)
    const uint32_t preA = (uint32_t)((((lane >> 4) << 4) ^ ((lane & 7) << 4)));
    const uint32_t preB = (uint32_t)((((lane & 8) << 1) ^ ((lane & 7) << 4)));
    const uint32_t rowA = (uint32_t)(lane & 15) * 128u;
    const uint32_t rowB = (uint32_t)(wn * 32 + (lane & 7) + ((lane >> 4) << 3)) * 128u;

    float acc[4][4][4];
    #pragma unroll
    for (int i = 0; i < 4; i++)
        #pragma unroll
        for (int j = 0; j < 4; j++)
            #pragma unroll
            for (int k = 0; k < 4; k++) acc[i][j][k] = 0.0f;

    // stage = 24KB: A(8KB) @ +0, B(16KB) @ +8192
    auto load_chunk = [&](int c) {
        const int buf = c & 1;
        const uint32_t offA = buf * 24576u;
        const uint32_t offB = offA + 8192u;
        const __half* Ag = A + (size_t)m0 * K + (size_t)c * 64;
        const __half* Bg = B + (size_t)n0 * K + (size_t)c * 64;
        #pragma unroll
        for (int t = 0; t < 4; t++) {          // A: 64 rows x 8 sixteens
            int idx = tid + t * 128;           // 0..511
            int row = idx >> 3;
            int c16 = idx & 7;
            uint32_t sw = (uint32_t)row * 128u
                        + (((uint32_t)c16 * 16u) ^ (((uint32_t)row & 7u) << 4));
            const void* ga = Ag + (size_t)row * K + c16 * 8;
            uint32_t na = (m0 + row < M) ? 16u : 0u;
            asm volatile("cp.async.cg.shared.global [%0], [%1], 16, %2;"
                         :: "r"(sb + offA + sw), "l"(ga), "r"(na));
        }
        #pragma unroll
        for (int t = 0; t < 8; t++) {          // B: 128 rows x 8 sixteens
            int idx = tid + t * 128;           // 0..1023
            int row = idx >> 3;
            int c16 = idx & 7;
            uint32_t sw = (uint32_t)row * 128u
                        + (((uint32_t)c16 * 16u) ^ (((uint32_t)row & 7u) << 4));
            const void* gb = Bg + (size_t)row * K + c16 * 8;
            asm volatile("cp.async.cg.shared.global [%0], [%1], 16;"
                         :: "r"(sb + offB + sw), "l"(gb));
        }
        asm volatile("cp.async.commit_group;" ::: "memory");
    };

    auto compute_chunk = [&](int buf) {
        const uint32_t baseA = sb + buf * 24576u + rowA;
        const uint32_t baseB = sb + buf * 24576u + 8192u + rowB;
        #pragma unroll
        for (int kk = 0; kk < 64; kk += 16) {
            const uint32_t cA = ((uint32_t)(2 * kk)) ^ preA;
            const uint32_t cB = ((uint32_t)(2 * kk)) ^ preB;
            uint32_t a[4][4];
            #pragma unroll
            for (int mi = 0; mi < 4; mi++) {
                asm volatile(
                    "ldmatrix.sync.aligned.m8n8.x4.shared.b16 {%0,%1,%2,%3}, [%4];"
                    : "=r"(a[mi][0]), "=r"(a[mi][1]), "=r"(a[mi][2]), "=r"(a[mi][3])
                    : "r"(baseA + (uint32_t)(mi * 2048) + cA));
            }
            uint32_t b[4][2];
            #pragma unroll
            for (int nj = 0; nj < 2; nj++) {
                uint32_t b0, b1, b2, b3;
                asm volatile(
                    "ldmatrix.sync.aligned.m8n8.x4.shared.b16 {%0,%1,%2,%3}, [%4];"
                    : "=r"(b0), "=r"(b1), "=r"(b2), "=r"(b3)
                    : "r"(baseB + (uint32_t)(nj * 2048) + cB));
                b[nj * 2 + 0][0] = b0; b[nj * 2 + 0][1] = b1;
                b[nj * 2 + 1][0] = b2; b[nj * 2 + 1][1] = b3;
            }
            #pragma unroll
            for (int mi = 0; mi < 4; mi++)
                #pragma unroll
                for (int ni = 0; ni < 4; ni++)
                    asm volatile(
                        "mma.sync.aligned.m16n8k16.row.col.f32.f16.f16.f32 "
                        "{%0,%1,%2,%3}, {%4,%5,%6,%7}, {%8,%9}, {%0,%1,%2,%3};"
                        : "+f"(acc[mi][ni][0]), "+f"(acc[mi][ni][1]),
                          "+f"(acc[mi][ni][2]), "+f"(acc[mi][ni][3])
                        : "r"(a[mi][0]), "r"(a[mi][1]), "r"(a[mi][2]), "r"(a[mi][3]),
                          "r"(b[ni][0]), "r"(b[ni][1]));
        }
    };

    load_chunk(0);
    for (int c = 0; c < nch; c++) {
        if (c + 1 < nch) {
            load_chunk(c + 1);
            asm volatile("cp.async.wait_group 1;" ::: "memory");
        } else {
            asm volatile("cp.async.wait_group 0;" ::: "memory");
        }
        __syncthreads();
        compute_chunk(c & 1);
        __syncthreads();
    }

    // ---- epilogue: gamma * acc + bias (+ exact GELU -> fp16) ----
    const float gamma = g_gamma[gslot];
    #pragma unroll
    for (int mi = 0; mi < 4; mi++) {
        #pragma unroll
        for (int half = 0; half < 2; half++) {
            int gr = m0 + mi * 16 + (lane >> 2) + half * 8;
            if (gr >= M) continue;
            #pragma unroll
            for (int ni = 0; ni < 4; ni++) {
                int gc = n0 + wn * 32 + ni * 8 + 2 * (lane & 3);
                float v0 = acc[mi][ni][half * 2 + 0] * gamma + bias[gc];
                float v1 = acc[mi][ni][half * 2 + 1] * gamma + bias[gc + 1];
                if (GELU_H) {
                    v0 = 0.5f * v0 * (1.0f + erff(v0 * 0.70710678118654752f));
                    v1 = 0.5f * v1 * (1.0f + erff(v1 * 0.70710678118654752f));
                    __half2 p;
                    p.x = __float2half_rn(v0);
                    p.y = __float2half_rn(v1);
                    *(__half2*)((__half*)Cout + (size_t)gr * N + gc) = p;
                } else {
                    *(float2*)((float*)Cout + (size_t)gr * N + gc) =
                        make_float2(v0, v1);
                }
            }
        }
    }
}

// ---------------------------------------------------------------------------
// Launch (5-launch structure kept so ncu lands on gemm1)
// ---------------------------------------------------------------------------
extern "C" void kernel_launch(void* const* d_in, const int* in_sizes, int n_in,
                              void* d_out, int out_size) {
    const float* x  = (const float*)d_in[0];
    const float* w1 = (const float*)d_in[1];
    const float* b1 = (const float*)d_in[2];
    const float* w2 = (const float*)d_in[3];
    const float* b2 = (const float*)d_in[4];
    float* out = (float*)d_out;

    __half *p_xh, *p_hh, *p_q1, *p_q2;
    cudaGetSymbolAddress((void**)&p_xh, g_xh);
    cudaGetSymbolAddress((void**)&p_hh, g_hh);
    cudaGetSymbolAddress((void**)&p_q1, g_q1);
    cudaGetSymbolAddress((void**)&p_q2, g_q2);

    const int NW = HQ * DQ;          // 2359296
    const int NX4 = MQ * DQ / 4;     // 2420736
    const int SMEM_DYN = 2 * 24576;  // 48KB: 2 stages x (A 8K + B 16K)

    static bool attr_done = false;
    if (!attr_done) {
        cudaFuncSetAttribute(hmma_gemm<1>,
            cudaFuncAttributeMaxDynamicSharedMemorySize, SMEM_DYN);
        cudaFuncSetAttribute(hmma_gemm<0>,
            cudaFuncAttributeMaxDynamicSharedMemorySize, SMEM_DYN);
        attr_done = true;
    }

    prep1_kernel<<<1024 + (NX4 + 255) / 256, 256>>>(w1, w2, NW, x, p_xh, NX4);
    finalize_gamma_kernel<<<1, 512>>>(NW, NW);
    quant_both_kernel<<<(2 * (NW / 4) + 255) / 256, 256>>>(w1, p_q1, w2, p_q2,
                                                           NW / 4);

    // GEMM1: [M, 768] x [H, 768]^T -> gelu -> fp16 h   (tiles 24 x 197)
    {
        dim3 grid(HQ / 128, MQ / 64);
        hmma_gemm<1><<<grid, 128, SMEM_DYN>>>(
            p_xh, p_q1, b1, (void*)p_hh, MQ, HQ, DQ, 0);
    }
    // GEMM2: [M, 3072] x [D, 3072]^T -> + b2 -> out fp32  (tiles 6 x 197)
    {
        dim3 grid(DQ / 128, MQ / 64);
        hmma_gemm<0><<<grid, 128, SMEM_DYN>>>(
            p_hh, p_q2, b2, (void*)out, MQ, DQ, HQ, 1);
    }
}

// round 14
// speedup vs baseline: 1.0883x; 1.0184x over previous
#include <cuda_runtime.h>
#include <cuda_fp16.h>
#include <math.h>
#include <stdint.h>

// Problem shape (fixed by the reference)
#define BQ 64
#define SQ 197
#define DQ 768
#define HQ 3072
#define MQ (BQ * SQ)  // 12608 = 197 * 64

// ---------------------------------------------------------------------------
// Device global scratch (no allocation allowed)
// ---------------------------------------------------------------------------
__device__ __half g_xh [(size_t)MQ * DQ];   // x in fp16
__device__ __half g_hh [(size_t)MQ * HQ];   // h (post-GELU) in fp16
__device__ __half g_q1 [(size_t)HQ * DQ];   // ternary w1 in fp16 (exact)
__device__ __half g_q2 [(size_t)DQ * HQ];   // ternary w2 in fp16 (exact)
__device__ float g_partial[1024];
__device__ float g_gamma[2];

__device__ __forceinline__ uint32_t smem_u32(const void* p) {
    uint32_t a;
    asm("{ .reg .u64 t; cvta.to.shared.u64 t, %1; cvt.u32.u64 %0, t; }"
        : "=r"(a) : "l"(p));
    return a;
}

__device__ __forceinline__ uint32_t pack_h2(float a, float b) {
    __half2 p;
    p.x = __float2half_rn(a);
    p.y = __float2half_rn(b);
    return *(uint32_t*)&p;
}

// ---------------------------------------------------------------------------
// prep1: blocks 0-511 abs(w1), 512-1023 abs(w2), rest cvt x (MLP=4).
// cvt partition: blocks (1024 + b), b in [0, 2364), each handles 1024 float4s
// as 4 coalesced rounds of 256.  2364*1024 == nx4 exactly.
// ---------------------------------------------------------------------------
__global__ void prep1_kernel(const float* __restrict__ w1,
                             const float* __restrict__ w2, int nw,
                             const float* __restrict__ x,
                             __half* __restrict__ xh, int nx4) {
    int b = blockIdx.x;
    if (b < 1024) {
        const float* w = (b < 512) ? w1 : w2;
        int slot = (b < 512) ? 0 : 1;
        int rb = b & 511;
        __shared__ float sdata[256];
        float s = 0.0f;
        for (int i = rb * blockDim.x + threadIdx.x; i < nw;
             i += 512 * blockDim.x)
            s += fabsf(w[i]);
        sdata[threadIdx.x] = s;
        __syncthreads();
        #pragma unroll
        for (int off = 128; off > 0; off >>= 1) {
            if (threadIdx.x < off) sdata[threadIdx.x] += sdata[threadIdx.x + off];
            __syncthreads();
        }
        if (threadIdx.x == 0) g_partial[slot * 512 + rb] = sdata[0];
    } else {
        int base = (b - 1024) * 1024 + threadIdx.x;
        float4 v[4];
        int idx[4];
        #pragma unroll
        for (int u = 0; u < 4; u++) {
            idx[u] = base + u * 256;
            if (idx[u] < nx4) v[u] = ((const float4*)x)[idx[u]];
        }
        #pragma unroll
        for (int u = 0; u < 4; u++) {
            if (idx[u] < nx4) {
                uint2 st = make_uint2(pack_h2(v[u].x, v[u].y),
                                      pack_h2(v[u].z, v[u].w));
                ((uint2*)xh)[idx[u]] = st;
            }
        }
    }
}

__global__ void finalize_gamma_kernel(int n1, int n2) {
    __shared__ float sdata[512];
    int t = threadIdx.x;
    sdata[t] = g_partial[t];
    __syncthreads();
    #pragma unroll
    for (int off = 256; off > 0; off >>= 1) {
        if (t < off) sdata[t] += sdata[t + off];
        __syncthreads();
    }
    if (t == 0) g_gamma[0] = sdata[0] / (float)n1 + 1e-5f;
    __syncthreads();
    sdata[t] = g_partial[512 + t];
    __syncthreads();
    #pragma unroll
    for (int off = 256; off > 0; off >>= 1) {
        if (t < off) sdata[t] += sdata[t + off];
        __syncthreads();
    }
    if (t == 0) g_gamma[1] = sdata[0] / (float)n2 + 1e-5f;
}

// ternarize BOTH weights (MLP=4): blocks [0,576) -> w1, [576,1152) -> w2;
// each block handles 1024 float4s (576*1024 == NW/4 exactly).
__global__ void quant_both_kernel(const float* __restrict__ w1,
                                  __half* __restrict__ q1,
                                  const float* __restrict__ w2,
                                  __half* __restrict__ q2, int n4) {
    int b = blockIdx.x;
    const float* w;
    __half* q;
    int slot, rb;
    if (b < 576) { w = w1; q = q1; slot = 0; rb = b; }
    else         { w = w2; q = q2; slot = 1; rb = b - 576; }
    float inv = 1.0f / g_gamma[slot];
    int base = rb * 1024 + threadIdx.x;
    float4 v[4];
    int idx[4];
    #pragma unroll
    for (int u = 0; u < 4; u++) {
        idx[u] = base + u * 256;
        if (idx[u] < n4) v[u] = ((const float4*)w)[idx[u]];
    }
    #pragma unroll
    for (int u = 0; u < 4; u++) {
        if (idx[u] < n4) {
            float t0 = fminf(1.0f, fmaxf(-1.0f, rintf(v[u].x * inv)));
            float t1 = fminf(1.0f, fmaxf(-1.0f, rintf(v[u].y * inv)));
            float t2 = fminf(1.0f, fmaxf(-1.0f, rintf(v[u].z * inv)));
            float t3 = fminf(1.0f, fmaxf(-1.0f, rintf(v[u].w * inv)));
            uint2 st = make_uint2(pack_h2(t0, t1), pack_h2(t2, t3));
            ((uint2*)q)[idx[u]] = st;
        }
    }
}

// ---------------------------------------------------------------------------
// HMMA GEMM (R13 engine, byte-identical): 64x128 CTA tile, 128 threads
// (4 warps x 64x32), 4 CTAs/SM, analytic swizzle, double-buffered cp.async.
// ---------------------------------------------------------------------------
template <int GELU_H>
__global__ __launch_bounds__(128, 4)
void hmma_gemm(const __half* __restrict__ A,
               const __half* __restrict__ B,
               const float* __restrict__ bias,
               void* __restrict__ Cout,
               int M, int N, int K, int gslot) {
    extern __shared__ char smem[];
    const uint32_t sb = smem_u32(smem);
    const int tid  = threadIdx.x;
    const int wid  = tid >> 5;      // 0..3 -> n-block of 32
    const int lane = tid & 31;
    const int m0 = blockIdx.y * 64;
    const int n0 = blockIdx.x * 128;
    const int wn = wid;

    const int nch = K >> 6;    // chunks of 64 fp16

    const uint32_t preA = (uint32_t)((((lane >> 4) << 4) ^ ((lane & 7) << 4)));
    const uint32_t preB = (uint32_t)((((lane & 8) << 1) ^ ((lane & 7) << 4)));
    const uint32_t rowA = (uint32_t)(lane & 15) * 128u;
    const uint32_t rowB = (uint32_t)(wn * 32 + (lane & 7) + ((lane >> 4) << 3)) * 128u;

    float acc[4][4][4];
    #pragma unroll
    for (int i = 0; i < 4; i++)
        #pragma unroll
        for (int j = 0; j < 4; j++)
            #pragma unroll
            for (int k = 0; k < 4; k++) acc[i][j][k] = 0.0f;

    auto load_chunk = [&](int c) {
        const int buf = c & 1;
        const uint32_t offA = buf * 24576u;
        const uint32_t offB = offA + 8192u;
        const __half* Ag = A + (size_t)m0 * K + (size_t)c * 64;
        const __half* Bg = B + (size_t)n0 * K + (size_t)c * 64;
        #pragma unroll
        for (int t = 0; t < 4; t++) {          // A: 64 rows x 8 sixteens
            int idx = tid + t * 128;
            int row = idx >> 3;
            int c16 = idx & 7;
            uint32_t sw = (uint32_t)row * 128u
                        + (((uint32_t)c16 * 16u) ^ (((uint32_t)row & 7u) << 4));
            const void* ga = Ag + (size_t)row * K + c16 * 8;
            uint32_t na = (m0 + row < M) ? 16u : 0u;
            asm volatile("cp.async.cg.shared.global [%0], [%1], 16, %2;"
                         :: "r"(sb + offA + sw), "l"(ga), "r"(na));
        }
        #pragma unroll
        for (int t = 0; t < 8; t++) {          // B: 128 rows x 8 sixteens
            int idx = tid + t * 128;
            int row = idx >> 3;
            int c16 = idx & 7;
            uint32_t sw = (uint32_t)row * 128u
                        + (((uint32_t)c16 * 16u) ^ (((uint32_t)row & 7u) << 4));
            const void* gb = Bg + (size_t)row * K + c16 * 8;
            asm volatile("cp.async.cg.shared.global [%0], [%1], 16;"
                         :: "r"(sb + offB + sw), "l"(gb));
        }
        asm volatile("cp.async.commit_group;" ::: "memory");
    };

    auto compute_chunk = [&](int buf) {
        const uint32_t baseA = sb + buf * 24576u + rowA;
        const uint32_t baseB = sb + buf * 24576u + 8192u + rowB;
        #pragma unroll
        for (int kk = 0; kk < 64; kk += 16) {
            const uint32_t cA = ((uint32_t)(2 * kk)) ^ preA;
            const uint32_t cB = ((uint32_t)(2 * kk)) ^ preB;
            uint32_t a[4][4];
            #pragma unroll
            for (int mi = 0; mi < 4; mi++) {
                asm volatile(
                    "ldmatrix.sync.aligned.m8n8.x4.shared.b16 {%0,%1,%2,%3}, [%4];"
                    : "=r"(a[mi][0]), "=r"(a[mi][1]), "=r"(a[mi][2]), "=r"(a[mi][3])
                    : "r"(baseA + (uint32_t)(mi * 2048) + cA));
            }
            uint32_t b[4][2];
            #pragma unroll
            for (int nj = 0; nj < 2; nj++) {
                uint32_t b0, b1, b2, b3;
                asm volatile(
                    "ldmatrix.sync.aligned.m8n8.x4.shared.b16 {%0,%1,%2,%3}, [%4];"
                    : "=r"(b0), "=r"(b1), "=r"(b2), "=r"(b3)
                    : "r"(baseB + (uint32_t)(nj * 2048) + cB));
                b[nj * 2 + 0][0] = b0; b[nj * 2 + 0][1] = b1;
                b[nj * 2 + 1][0] = b2; b[nj * 2 + 1][1] = b3;
            }
            #pragma unroll
            for (int mi = 0; mi < 4; mi++)
                #pragma unroll
                for (int ni = 0; ni < 4; ni++)
                    asm volatile(
                        "mma.sync.aligned.m16n8k16.row.col.f32.f16.f16.f32 "
                        "{%0,%1,%2,%3}, {%4,%5,%6,%7}, {%8,%9}, {%0,%1,%2,%3};"
                        : "+f"(acc[mi][ni][0]), "+f"(acc[mi][ni][1]),
                          "+f"(acc[mi][ni][2]), "+f"(acc[mi][ni][3])
                        : "r"(a[mi][0]), "r"(a[mi][1]), "r"(a[mi][2]), "r"(a[mi][3]),
                          "r"(b[ni][0]), "r"(b[ni][1]));
        }
    };

    load_chunk(0);
    for (int c = 0; c < nch; c++) {
        if (c + 1 < nch) {
            load_chunk(c + 1);
            asm volatile("cp.async.wait_group 1;" ::: "memory");
        } else {
            asm volatile("cp.async.wait_group 0;" ::: "memory");
        }
        __syncthreads();
        compute_chunk(c & 1);
        __syncthreads();
    }

    // ---- epilogue: gamma * acc + bias (+ exact GELU -> fp16) ----
    const float gamma = g_gamma[gslot];
    #pragma unroll
    for (int mi = 0; mi < 4; mi++) {
        #pragma unroll
        for (int half = 0; half < 2; half++) {
            int gr = m0 + mi * 16 + (lane >> 2) + half * 8;
            if (gr >= M) continue;
            #pragma unroll
            for (int ni = 0; ni < 4; ni++) {
                int gc = n0 + wn * 32 + ni * 8 + 2 * (lane & 3);
                float v0 = acc[mi][ni][half * 2 + 0] * gamma + bias[gc];
                float v1 = acc[mi][ni][half * 2 + 1] * gamma + bias[gc + 1];
                if (GELU_H) {
                    v0 = 0.5f * v0 * (1.0f + erff(v0 * 0.70710678118654752f));
                    v1 = 0.5f * v1 * (1.0f + erff(v1 * 0.70710678118654752f));
                    __half2 p;
                    p.x = __float2half_rn(v0);
                    p.y = __float2half_rn(v1);
                    *(__half2*)((__half*)Cout + (size_t)gr * N + gc) = p;
                } else {
                    *(float2*)((float*)Cout + (size_t)gr * N + gc) =
                        make_float2(v0, v1);
                }
            }
        }
    }
}

// ---------------------------------------------------------------------------
// Launch
// ---------------------------------------------------------------------------
extern "C" void kernel_launch(void* const* d_in, const int* in_sizes, int n_in,
                              void* d_out, int out_size) {
    const float* x  = (const float*)d_in[0];
    const float* w1 = (const float*)d_in[1];
    const float* b1 = (const float*)d_in[2];
    const float* w2 = (const float*)d_in[3];
    const float* b2 = (const float*)d_in[4];
    float* out = (float*)d_out;

    __half *p_xh, *p_hh, *p_q1, *p_q2;
    cudaGetSymbolAddress((void**)&p_xh, g_xh);
    cudaGetSymbolAddress((void**)&p_hh, g_hh);
    cudaGetSymbolAddress((void**)&p_q1, g_q1);
    cudaGetSymbolAddress((void**)&p_q2, g_q2);

    const int NW = HQ * DQ;          // 2359296
    const int NX4 = MQ * DQ / 4;     // 2420736 = 2364 * 1024
    const int SMEM_DYN = 2 * 24576;  // 48KB

    static bool attr_done = false;
    if (!attr_done) {
        cudaFuncSetAttribute(hmma_gemm<1>,
            cudaFuncAttributeMaxDynamicSharedMemorySize, SMEM_DYN);
        cudaFuncSetAttribute(hmma_gemm<0>,
            cudaFuncAttributeMaxDynamicSharedMemorySize, SMEM_DYN);
        attr_done = true;
    }

    prep1_kernel<<<1024 + NX4 / 1024, 256>>>(w1, w2, NW, x, p_xh, NX4);
    finalize_gamma_kernel<<<1, 512>>>(NW, NW);
    quant_both_kernel<<<1152, 256>>>(w1, p_q1, w2, p_q2, NW / 4);

    // GEMM1: [M, 768] x [H, 768]^T -> gelu -> fp16 h
    {
        dim3 grid(HQ / 128, MQ / 64);
        hmma_gemm<1><<<grid, 128, SMEM_DYN>>>(
            p_xh, p_q1, b1, (void*)p_hh, MQ, HQ, DQ, 0);
    }
    // GEMM2: [M, 3072] x [D, 3072]^T -> + b2 -> out fp32
    {
        dim3 grid(DQ / 128, MQ / 64);
        hmma_gemm<0><<<grid, 128, SMEM_DYN>>>(
            p_hh, p_q2, b2, (void*)out, MQ, DQ, HQ, 1);
    }
}